// round 7
// baseline (speedup 1.0000x reference)
#include <cuda_runtime.h>
#include <cuda_fp16.h>
#include <math.h>
#include <stdint.h>

#define ROI   116
#define FEAT  6670      // ROI*(ROI-1)/2
#define FEATP 6720      // padded to multiple of 64
#define NB    64        // batch
#define NW    128       // bags per batch
#define BW    8192      // NB*NW
#define DD    1024
#define HH    1024
#define NSTG  (FEATP / 32)   // 210 K-stages of 32
#define NTILE 512            // (BW/128) * (DD/128)

// ---------------- scratch (device globals; no allocation) ----------------
__device__ __align__(16) __half g_bag[(size_t)BW * FEATP];   // 110 MB
__device__ __align__(16) __half g_w1th[(size_t)DD * FEATP];  // 13.8 MB  [N][K]
__device__ int   g_off[FEAT];
__device__ float g_a[BW];
__device__ float g_att[BW];
__device__ float g_bagz0[NB * FEATP];
__device__ float g_bagz[NB * FEATP];
__device__ float g_ccn[2 * FEATP];
__device__ float g_q[NB * HH];
__device__ float g_k2[2 * HH];
__device__ float g_v2[2 * HH];
__device__ float g_fcx[NB * HH];
__device__ float g_t1[NB * DD];

// ---------------- PTX helpers (generic, sm_80-level) ----------------
__device__ __forceinline__ uint32_t smem_u32(const void* p) {
    uint32_t a;
    asm("{ .reg .u64 t; cvta.to.shared.u64 t, %1; cvt.u32.u64 %0, t; }" : "=r"(a) : "l"(p));
    return a;
}
#define CP_ASYNC16(dst, src) \
    asm volatile("cp.async.cg.shared.global [%0], [%1], 16;" \
                 :: "r"(dst), "l"(src) : "memory")
#define CP_COMMIT() asm volatile("cp.async.commit_group;" ::: "memory")
#define CP_WAIT(n)  asm volatile("cp.async.wait_group %0;" :: "n"(n) : "memory")

__device__ __forceinline__ void ldm_x4(uint32_t& r0, uint32_t& r1, uint32_t& r2, uint32_t& r3,
                                       uint32_t addr) {
    asm volatile("ldmatrix.sync.aligned.m8n8.x4.shared.b16 {%0,%1,%2,%3}, [%4];"
                 : "=r"(r0), "=r"(r1), "=r"(r2), "=r"(r3) : "r"(addr));
}
__device__ __forceinline__ void mma16816(float* c, const uint32_t* a, const uint32_t* b) {
    asm volatile(
        "mma.sync.aligned.m16n8k16.row.col.f32.f16.f16.f32 "
        "{%0,%1,%2,%3}, {%4,%5,%6,%7}, {%8,%9}, {%0,%1,%2,%3};"
        : "+f"(c[0]), "+f"(c[1]), "+f"(c[2]), "+f"(c[3])
        : "r"(a[0]), "r"(a[1]), "r"(a[2]), "r"(a[3]), "r"(b[0]), "r"(b[1]));
}
__device__ __forceinline__ float fast_tanh(float x) {
    float e = __expf(2.0f * x);
    return 1.0f - 2.0f / (e + 1.0f);
}

// ---------------- triu index table ----------------
__global__ void init_off_kernel() {
    int i = blockIdx.x;
    int base = i * (ROI - 1) - i * (i - 1) / 2;
    int cnt = ROI - 1 - i;
    for (int jj = threadIdx.x; jj < cnt; jj += blockDim.x)
        g_off[base + jj] = i * ROI + (i + 1 + jj);
}

// ---------------- gather -> fp16 ----------------
__global__ void gather_kernel(const float* __restrict__ FC) {
    int bw = blockIdx.y;
    int f = blockIdx.x * 256 + threadIdx.x;
    if (f < FEATP) {
        float v = 0.f;
        if (f < FEAT) v = FC[(size_t)bw * (ROI * ROI) + g_off[f]];
        g_bag[(size_t)bw * FEATP + f] = __float2half_rn(v);
    }
}

// ---------------- W1 -> W1T fp16 ([N][K], padded) ----------------
__global__ void w1t_kernel(const float* __restrict__ W1) {
    __shared__ float t[32][33];
    int kb = blockIdx.x * 32, nb = blockIdx.y * 32;
    int tx = threadIdx.x, ty = threadIdx.y;
#pragma unroll
    for (int i = 0; i < 32; i += 8) {
        int k = kb + ty + i;
        t[ty + i][tx] = (k < FEAT) ? W1[(size_t)k * DD + nb + tx] : 0.f;
    }
    __syncthreads();
#pragma unroll
    for (int i = 0; i < 32; i += 8) {
        float v = t[tx][ty + i];
        g_w1th[(size_t)(nb + ty + i) * FEATP + kb + tx] = __float2half_rn(v);
    }
}

// ---------------- init biases into accumulator buffers ----------------
__global__ void init_misc_kernel(const float* __restrict__ b2,
                                 const float* __restrict__ bq,
                                 const float* __restrict__ bk,
                                 const float* __restrict__ bc1) {
    int idx = blockIdx.x * 256 + threadIdx.x;
    if (idx < BW) { g_a[idx] = b2[0]; return; }
    idx -= BW;
    if (idx < NB * HH) { g_q[idx] = bq[idx & (HH - 1)]; return; }
    idx -= NB * HH;
    if (idx < 2 * HH) { g_k2[idx] = bk[idx & (HH - 1)]; return; }
    idx -= 2 * HH;
    if (idx < 2 * HH) { g_v2[idx] = bq[idx & (HH - 1)]; return; }
    idx -= 2 * HH;
    if (idx < NB * DD) { g_t1[idx] = bc1[idx & (DD - 1)]; return; }
}

// ---------------- HMMA GEMM: S = bag @ W1T^T (fp16), fused tanh/W2 epi ----
// Persistent CTAs. CTA tile 128x128, warp tile 32x128 (4 warps, 128 threads).
// K-stage 32, 4-stage cp.async pipeline, one sync per stage.
#define LDA       80
#define TILE_B    10240                // 128 rows x 80B
#define STAGE_B   (2 * TILE_B)        // A + B = 20480
#define GEMM_SMEM (4 * STAGE_B)       // 81920

__device__ __forceinline__ void load_stage(uint32_t sdst, int k0, int m0, int n0, int tid) {
    uint32_t so = sdst + tid * LDA;
    size_t ga = ((size_t)(m0 + tid) * FEATP + k0) * 2;
    size_t gb = ((size_t)(n0 + tid) * FEATP + k0) * 2;
    unsigned long long pa = __cvta_generic_to_global((const char*)g_bag + ga);
    unsigned long long pb = __cvta_generic_to_global((const char*)g_w1th + gb);
    CP_ASYNC16(so,      pa);      CP_ASYNC16(so + 16, pa + 16);
    CP_ASYNC16(so + 32, pa + 32); CP_ASYNC16(so + 48, pa + 48);
    so += TILE_B;
    CP_ASYNC16(so,      pb);      CP_ASYNC16(so + 16, pb + 16);
    CP_ASYNC16(so + 32, pb + 32); CP_ASYNC16(so + 48, pb + 48);
}

__global__ __launch_bounds__(128, 2) void gemm_mma_kernel(const float* __restrict__ b1,
                                                          const float* __restrict__ W2) {
    extern __shared__ char sm[];
    const uint32_t sbase = smem_u32(sm);
    const int tid = threadIdx.x, lane = tid & 31, wm = tid >> 5;   // 4 M-warps
    const uint32_t aRowOfs = (uint32_t)(wm * 32 + (lane & 15)) * LDA
                           + (uint32_t)(lane >> 4) * 16;
    const uint32_t bRowOfs = (uint32_t)((lane >> 4) * 8 + (lane & 7)) * LDA
                           + (uint32_t)((lane >> 3) & 1) * 16;
    const int g = lane >> 2, t4 = lane & 3;

    for (int t = blockIdx.x; t < NTILE; t += gridDim.x) {
        const int n0 = (t & 7) * 128, m0 = (t >> 3) * 128;

        float acc[2][16][4];
#pragma unroll
        for (int mt = 0; mt < 2; mt++)
#pragma unroll
            for (int nt = 0; nt < 16; nt++)
#pragma unroll
                for (int c = 0; c < 4; c++) acc[mt][nt][c] = 0.f;

        load_stage(sbase, 0, m0, n0, tid);                CP_COMMIT();
        load_stage(sbase + STAGE_B, 32, m0, n0, tid);     CP_COMMIT();
        load_stage(sbase + 2 * STAGE_B, 64, m0, n0, tid); CP_COMMIT();

        int slot = 0;
        for (int i = 0; i < NSTG; i++) {
            if (i < NSTG - 2)       { CP_WAIT(2); }
            else if (i == NSTG - 2) { CP_WAIT(1); }
            else                    { CP_WAIT(0); }
            __syncthreads();
            if (i + 3 < NSTG) {
                int ns = slot + 3; if (ns >= 4) ns -= 4;
                load_stage(sbase + ns * STAGE_B, (i + 3) * 32, m0, n0, tid);
                CP_COMMIT();
            }
            const uint32_t st = sbase + (uint32_t)slot * STAGE_B;
#pragma unroll
            for (int kk = 0; kk < 2; kk++) {
                uint32_t aH[2][4], bb[16][2];
#pragma unroll
                for (int mt = 0; mt < 2; mt++)
                    ldm_x4(aH[mt][0], aH[mt][1], aH[mt][2], aH[mt][3],
                           st + aRowOfs + (uint32_t)mt * 16 * LDA + kk * 32);
#pragma unroll
                for (int p = 0; p < 8; p++)
                    ldm_x4(bb[2 * p][0], bb[2 * p][1], bb[2 * p + 1][0], bb[2 * p + 1][1],
                           st + TILE_B + bRowOfs + (uint32_t)p * 16 * LDA + kk * 32);
#pragma unroll
                for (int mt = 0; mt < 2; mt++)
#pragma unroll
                    for (int nt = 0; nt < 16; nt++) mma16816(acc[mt][nt], aH[mt], bb[nt]);
            }
            if (++slot == 4) slot = 0;
        }

        // epilogue: per-row sum over this 128-col block of tanh(S+b1)*W2
#pragma unroll
        for (int mt = 0; mt < 2; mt++) {
            float sA = 0.f, sB = 0.f;
#pragma unroll
            for (int nt = 0; nt < 16; nt++) {
                int c0 = n0 + nt * 8 + 2 * t4;
                float b1a = b1[c0], b1b = b1[c0 + 1];
                float w2a = W2[c0], w2b = W2[c0 + 1];
                sA += fast_tanh(acc[mt][nt][0] + b1a) * w2a + fast_tanh(acc[mt][nt][1] + b1b) * w2b;
                sB += fast_tanh(acc[mt][nt][2] + b1a) * w2a + fast_tanh(acc[mt][nt][3] + b1b) * w2b;
            }
            sA += __shfl_xor_sync(0xFFFFFFFF, sA, 1);
            sA += __shfl_xor_sync(0xFFFFFFFF, sA, 2);
            sB += __shfl_xor_sync(0xFFFFFFFF, sB, 1);
            sB += __shfl_xor_sync(0xFFFFFFFF, sB, 2);
            if (t4 == 0) {
                int r = m0 + wm * 32 + mt * 16 + g;
                atomicAdd(&g_a[r], sA);
                atomicAdd(&g_a[r + 8], sB);
            }
        }
        __syncthreads();   // protect smem before next tile's prologue
    }
}

// ---------------- softmax over W per batch ----------------
__global__ void softmax_kernel() {
    int b = blockIdx.x, t = threadIdx.x;  // 128 threads
    __shared__ float sv[128];
    float v = g_a[b * NW + t];
    sv[t] = v; __syncthreads();
    for (int s = 64; s > 0; s >>= 1) { if (t < s) sv[t] = fmaxf(sv[t], sv[t + s]); __syncthreads(); }
    float m = sv[0]; __syncthreads();
    float e = expf(v - m);
    sv[t] = e; __syncthreads();
    for (int s = 64; s > 0; s >>= 1) { if (t < s) sv[t] += sv[t + s]; __syncthreads(); }
    g_att[b * NW + t] = e / sv[0];
}

// ---------------- attention pool ----------------
__global__ void pool_kernel() {
    int b = blockIdx.y;
    int f = blockIdx.x * 256 + threadIdx.x;
    __shared__ float sat[NW];
    if (threadIdx.x < NW) sat[threadIdx.x] = g_att[b * NW + threadIdx.x];
    __syncthreads();
    if (f >= FEAT) return;
    float acc = 0.f;
    const __half* bh = g_bag + (size_t)b * NW * FEATP + f;
#pragma unroll 4
    for (int w = 0; w < NW; w++)
        acc += sat[w] * __half2float(bh[(size_t)w * FEATP]);
    g_bagz0[b * FEATP + f] = acc;
}

// ---------------- batchnorms ----------------
__global__ void bn_kernel(const float* __restrict__ cc,
                          const float* __restrict__ bn_g, const float* __restrict__ bn_b,
                          const float* __restrict__ bn2_g, const float* __restrict__ bn2_b) {
    int f = blockIdx.x * 256 + threadIdx.x;
    if (f >= FEAT) return;
    float mu = 0.f;
    for (int b = 0; b < NB; b++) mu += g_bagz0[b * FEATP + f];
    mu *= (1.f / NB);
    float var = 0.f;
    for (int b = 0; b < NB; b++) { float d = g_bagz0[b * FEATP + f] - mu; var += d * d; }
    var *= (1.f / NB);
    float inv = rsqrtf(var + 1e-5f);
    float g = bn_g[f], bt = bn_b[f];
    for (int b = 0; b < NB; b++)
        g_bagz[b * FEATP + f] = (g_bagz0[b * FEATP + f] - mu) * inv * g + bt;
    float c0 = cc[f], c1 = cc[FEAT + f];
    float mu2 = 0.5f * (c0 + c1);
    float d0 = c0 - mu2, d1 = c1 - mu2;
    float inv2 = rsqrtf(0.5f * (d0 * d0 + d1 * d1) + 1e-5f);
    float g2 = bn2_g[f], b2v = bn2_b[f];
    g_ccn[f] = d0 * inv2 * g2 + b2v;
    g_ccn[FEATP + f] = d1 * inv2 * g2 + b2v;
}

// ---------------- skinny GEMM: C[M,N] += A[M,K] @ B[K,N], split-K atomics ----
// Unroll-4 B prefetch -> MLP=4 to hide L2 latency.
template <int M>
__global__ __launch_bounds__(256) void skinny_kernel(int selA, int lda,
                                                     const float* __restrict__ B, int ldb,
                                                     int selC, int K, int N) {
    const float* A = (selA == 0) ? g_bagz : (selA == 1) ? g_ccn : g_fcx;
    float* C = (selC == 0) ? g_q : (selC == 1) ? g_k2 : (selC == 2) ? g_v2 : g_t1;
    __shared__ float sA[M][33];
    int tid = threadIdx.x;
    int col = blockIdx.x * 256 + tid;
    int nsplit = gridDim.y;
    int len = (K + nsplit - 1) / nsplit;
    int k0 = blockIdx.y * len;
    int kend = min(K, k0 + len);
    float acc[M];
#pragma unroll
    for (int m = 0; m < M; m++) acc[m] = 0.f;
    for (int kb = k0; kb < kend; kb += 32) {
        int kmax = min(32, kend - kb);
        for (int idx = tid; idx < M * 32; idx += 256) {
            int m = idx >> 5, kk = idx & 31;
            sA[m][kk] = (kk < kmax) ? A[(size_t)m * lda + kb + kk] : 0.f;
        }
        __syncthreads();
        if (col < N) {
            const float* Bp = B + (size_t)kb * ldb + col;
            int kk = 0;
            for (; kk + 4 <= kmax; kk += 4) {
                float bv0 = Bp[0];
                float bv1 = Bp[(size_t)ldb];
                float bv2 = Bp[2 * (size_t)ldb];
                float bv3 = Bp[3 * (size_t)ldb];
                Bp += 4 * (size_t)ldb;
#pragma unroll
                for (int m = 0; m < M; m++) acc[m] += sA[m][kk] * bv0;
#pragma unroll
                for (int m = 0; m < M; m++) acc[m] += sA[m][kk + 1] * bv1;
#pragma unroll
                for (int m = 0; m < M; m++) acc[m] += sA[m][kk + 2] * bv2;
#pragma unroll
                for (int m = 0; m < M; m++) acc[m] += sA[m][kk + 3] * bv3;
            }
            for (; kk < kmax; kk++) {
                float bv = Bp[0]; Bp += (size_t)ldb;
#pragma unroll
                for (int m = 0; m < M; m++) acc[m] += sA[m][kk] * bv;
            }
        }
        __syncthreads();
    }
    if (col < N) {
#pragma unroll
        for (int m = 0; m < M; m++) atomicAdd(&C[(size_t)m * N + col], acc[m]);
    }
}

// ---------------- cross attention ----------------
__global__ void cross_kernel() {
    __shared__ float sQK[64][2];
    __shared__ float sac[64][2];
    int t = threadIdx.x;  // 256
    if (t < 128) {
        int b = t >> 1, r = t & 1;
        const float* qp = g_q + b * HH;
        const float* kp = g_k2 + r * HH;
        float acc = 0.f;
        for (int d = 0; d < HH; d++) acc += qp[d] * kp[d];
        sQK[b][r] = acc * (1.0f / 32.0f);
    }
    __syncthreads();
    if (t < 64) {
        float x0 = sQK[t][0], x1 = sQK[t][1];
        float m = fmaxf(x0, x1);
        float e0 = expf(x0 - m), e1 = expf(x1 - m);
        float inv = 1.f / (e0 + e1);
        sac[t][0] = e0 * inv; sac[t][1] = e1 * inv;
    }
    __syncthreads();
    for (int idx = t; idx < NB * HH; idx += 256) {
        int b = idx >> 10, d = idx & 1023;
        g_fcx[idx] = sac[b][0] * g_v2[d] + sac[b][1] * g_v2[HH + d];
    }
}

// ---------------- classifier head ----------------
__global__ void final_kernel(const float* __restrict__ Wc2, const float* __restrict__ bc2,
                             float* __restrict__ out, int out_size) {
    int b = blockIdx.x, t = threadIdx.x;
    float acc = 0.f;
    for (int d = t; d < DD; d += 256) acc += fmaxf(g_t1[b * DD + d], 0.f) * Wc2[d];
    __shared__ float red[256];
    red[t] = acc; __syncthreads();
    for (int s = 128; s > 0; s >>= 1) { if (t < s) red[t] += red[t + s]; __syncthreads(); }
    if (t == 0) {
        float y = 1.f / (1.f + expf(-(red[0] + bc2[0])));
        out[b] = y;
        if (64 + b < out_size) out[64 + b] = (y >= 0.5f) ? 1.f : 0.f;
    }
}

// ---------------- launch ----------------
extern "C" void kernel_launch(void* const* d_in, const int* in_sizes, int n_in,
                              void* d_out, int out_size) {
    const float* FC    = (const float*)d_in[0];
    const float* cc    = (const float*)d_in[1];
    const float* W1    = (const float*)d_in[2];
    const float* b1    = (const float*)d_in[3];
    const float* W2    = (const float*)d_in[4];
    const float* b2    = (const float*)d_in[5];
    const float* bn_g  = (const float*)d_in[6];
    const float* bn_b  = (const float*)d_in[7];
    const float* bn2_g = (const float*)d_in[8];
    const float* bn2_b = (const float*)d_in[9];
    const float* Wq    = (const float*)d_in[10];
    const float* bq    = (const float*)d_in[11];
    const float* Wk    = (const float*)d_in[12];
    const float* bk    = (const float*)d_in[13];
    const float* Wc1   = (const float*)d_in[14];
    const float* bc1   = (const float*)d_in[15];
    const float* Wc2   = (const float*)d_in[16];
    const float* bc2   = (const float*)d_in[17];
    float* out = (float*)d_out;

    cudaFuncSetAttribute(gemm_mma_kernel, cudaFuncAttributeMaxDynamicSharedMemorySize, GEMM_SMEM);

    init_off_kernel<<<ROI - 1, 128>>>();
    gather_kernel<<<dim3((FEATP + 255) / 256, BW), 256>>>(FC);
    w1t_kernel<<<dim3(FEATP / 32, DD / 32), dim3(32, 8)>>>(W1);
    init_misc_kernel<<<(BW + NB * HH + 4 * HH + NB * DD + 255) / 256, 256>>>(b2, bq, bk, bc1);
    gemm_mma_kernel<<<304, 128, GEMM_SMEM>>>(b1, W2);
    softmax_kernel<<<NB, 128>>>();
    pool_kernel<<<dim3((FEAT + 255) / 256, NB), 256>>>();
    bn_kernel<<<(FEAT + 255) / 256, 256>>>(cc, bn_g, bn_b, bn2_g, bn2_b);
    skinny_kernel<64><<<dim3(4, 52), 256>>>(0, FEATP, Wq, HH, 0, FEAT, HH);
    skinny_kernel<2><<<dim3(4, 8), 256>>>(1, FEATP, Wk, HH, 1, FEAT, HH);
    skinny_kernel<2><<<dim3(4, 8), 256>>>(1, FEATP, Wq, HH, 2, FEAT, HH);
    cross_kernel<<<1, 256>>>();
    skinny_kernel<64><<<dim3(4, 8), 256>>>(2, HH, Wc1, DD, 3, HH, DD);
    skinny_kernel<64><<<dim3(4, 52), 256>>>(0, FEATP, Wc1 + (size_t)HH * DD, DD, 3, FEAT, DD);
    final_kernel<<<NB, 256>>>(Wc2, bc2, out, out_size);
}

// round 8
// speedup vs baseline: 1.1697x; 1.1697x over previous
#include <cuda_runtime.h>
#include <cuda_fp16.h>
#include <math.h>
#include <stdint.h>

#define ROI   116
#define FEAT  6670      // ROI*(ROI-1)/2
#define FEATP 6720      // padded to multiple of 64
#define NB    64        // batch
#define NW    128       // bags per batch
#define BW    8192      // NB*NW
#define DD    1024
#define HH    1024
#define NSTG64 (FEATP / 64)  // 105 K-stages of 64

// ---------------- scratch (device globals; no allocation) ----------------
__device__ __align__(16) __half g_bag[(size_t)BW * FEATP];   // 110 MB
__device__ __align__(16) __half g_w1th[(size_t)DD * FEATP];  // 13.8 MB  [N][K]
__device__ int   g_off[FEAT];
__device__ float g_a[BW];
__device__ float g_att[BW];
__device__ float g_bagz0[NB * FEATP];
__device__ float g_bagz[NB * FEATP];
__device__ float g_ccn[2 * FEATP];
__device__ float g_q[NB * HH];
__device__ float g_k2[2 * HH];
__device__ float g_v2[2 * HH];
__device__ float g_fcx[NB * HH];
__device__ float g_t1[NB * DD];

// ---------------- PTX helpers (generic, sm_80-level) ----------------
__device__ __forceinline__ uint32_t smem_u32(const void* p) {
    uint32_t a;
    asm("{ .reg .u64 t; cvta.to.shared.u64 t, %1; cvt.u32.u64 %0, t; }" : "=r"(a) : "l"(p));
    return a;
}
#define CP_ASYNC16(dst, src) \
    asm volatile("cp.async.cg.shared.global [%0], [%1], 16;" \
                 :: "r"(dst), "l"(src) : "memory")
#define CP_COMMIT() asm volatile("cp.async.commit_group;" ::: "memory")
#define CP_WAIT(n)  asm volatile("cp.async.wait_group %0;" :: "n"(n) : "memory")

__device__ __forceinline__ void ldm_x4(uint32_t& r0, uint32_t& r1, uint32_t& r2, uint32_t& r3,
                                       uint32_t addr) {
    asm volatile("ldmatrix.sync.aligned.m8n8.x4.shared.b16 {%0,%1,%2,%3}, [%4];"
                 : "=r"(r0), "=r"(r1), "=r"(r2), "=r"(r3) : "r"(addr));
}
__device__ __forceinline__ void mma16816(float* c, const uint32_t* a, const uint32_t* b) {
    asm volatile(
        "mma.sync.aligned.m16n8k16.row.col.f32.f16.f16.f32 "
        "{%0,%1,%2,%3}, {%4,%5,%6,%7}, {%8,%9}, {%0,%1,%2,%3};"
        : "+f"(c[0]), "+f"(c[1]), "+f"(c[2]), "+f"(c[3])
        : "r"(a[0]), "r"(a[1]), "r"(a[2]), "r"(a[3]), "r"(b[0]), "r"(b[1]));
}
__device__ __forceinline__ float fast_tanh(float x) {
    float e = __expf(2.0f * x);
    return 1.0f - 2.0f / (e + 1.0f);
}

// ---------------- triu index table ----------------
__global__ void init_off_kernel() {
    int i = blockIdx.x;
    int base = i * (ROI - 1) - i * (i - 1) / 2;
    int cnt = ROI - 1 - i;
    for (int jj = threadIdx.x; jj < cnt; jj += blockDim.x)
        g_off[base + jj] = i * ROI + (i + 1 + jj);
}

// ---------------- gather -> fp16 ----------------
__global__ void gather_kernel(const float* __restrict__ FC) {
    int bw = blockIdx.y;
    int f = blockIdx.x * 256 + threadIdx.x;
    if (f < FEATP) {
        float v = 0.f;
        if (f < FEAT) v = FC[(size_t)bw * (ROI * ROI) + g_off[f]];
        g_bag[(size_t)bw * FEATP + f] = __float2half_rn(v);
    }
}

// ---------------- W1 -> W1T fp16 ([N][K], padded) ----------------
__global__ void w1t_kernel(const float* __restrict__ W1) {
    __shared__ float t[32][33];
    int kb = blockIdx.x * 32, nb = blockIdx.y * 32;
    int tx = threadIdx.x, ty = threadIdx.y;
#pragma unroll
    for (int i = 0; i < 32; i += 8) {
        int k = kb + ty + i;
        t[ty + i][tx] = (k < FEAT) ? W1[(size_t)k * DD + nb + tx] : 0.f;
    }
    __syncthreads();
#pragma unroll
    for (int i = 0; i < 32; i += 8) {
        float v = t[tx][ty + i];
        g_w1th[(size_t)(nb + ty + i) * FEATP + kb + tx] = __float2half_rn(v);
    }
}

// ---------------- init biases into accumulator buffers ----------------
__global__ void init_misc_kernel(const float* __restrict__ b2,
                                 const float* __restrict__ bq,
                                 const float* __restrict__ bk,
                                 const float* __restrict__ bc1) {
    int idx = blockIdx.x * 256 + threadIdx.x;
    if (idx < BW) { g_a[idx] = b2[0]; return; }
    idx -= BW;
    if (idx < NB * HH) { g_q[idx] = bq[idx & (HH - 1)]; return; }
    idx -= NB * HH;
    if (idx < 2 * HH) { g_k2[idx] = bk[idx & (HH - 1)]; return; }
    idx -= 2 * HH;
    if (idx < 2 * HH) { g_v2[idx] = bq[idx & (HH - 1)]; return; }
    idx -= 2 * HH;
    if (idx < NB * DD) { g_t1[idx] = bc1[idx & (DD - 1)]; return; }
}

// ---------------- HMMA GEMM: S = bag @ W1T^T (fp16), fused tanh/W2 epi ----
// CTA 128x128, 8 warps (4Mx2N), warp tile 32x64. K-stage 64, 2-stage double
// buffer, ONE __syncthreads per stage. smem rows 144B (128 data + 16 pad).
#define LDA       144
#define TILE_B    18432               // 128 rows x 144B
#define STAGE_B   (2 * TILE_B)        // A + B = 36864
#define GEMM_SMEM (2 * STAGE_B)       // 73728

__device__ __forceinline__ void load_stage(uint32_t sdst, int k0, int m0, int n0, int tid) {
    int row = tid >> 1;
    int cb = (tid & 1) * 64;          // byte offset within 128B row half
    uint32_t so = sdst + row * LDA + cb;
    size_t ga = ((size_t)(m0 + row) * FEATP + k0) * 2 + cb;
    size_t gb = ((size_t)(n0 + row) * FEATP + k0) * 2 + cb;
    unsigned long long pa = __cvta_generic_to_global((const char*)g_bag + ga);
    unsigned long long pb = __cvta_generic_to_global((const char*)g_w1th + gb);
    CP_ASYNC16(so,      pa);      CP_ASYNC16(so + 16, pa + 16);
    CP_ASYNC16(so + 32, pa + 32); CP_ASYNC16(so + 48, pa + 48);
    so += TILE_B;
    CP_ASYNC16(so,      pb);      CP_ASYNC16(so + 16, pb + 16);
    CP_ASYNC16(so + 32, pb + 32); CP_ASYNC16(so + 48, pb + 48);
}

__global__ __launch_bounds__(256, 2) void gemm_mma_kernel(const float* __restrict__ b1,
                                                          const float* __restrict__ W2) {
    extern __shared__ char sm[];
    const uint32_t sbase = smem_u32(sm);
    const int tid = threadIdx.x, lane = tid & 31, wid = tid >> 5;
    const int wm = wid & 3, wn = wid >> 2;        // 4 M-warps x 2 N-warps
    const int n0 = blockIdx.x * 128, m0 = blockIdx.y * 128;

    float acc[2][8][4];
#pragma unroll
    for (int mt = 0; mt < 2; mt++)
#pragma unroll
        for (int nt = 0; nt < 8; nt++)
#pragma unroll
            for (int c = 0; c < 4; c++) acc[mt][nt][c] = 0.f;

    load_stage(sbase, 0, m0, n0, tid);
    CP_COMMIT();

    const uint32_t aRowOfs = (uint32_t)(wm * 32 + ((lane >> 3) & 1) * 8 + (lane & 7)) * LDA
                           + (uint32_t)(lane >> 4) * 16;
    const uint32_t bRowOfs = (uint32_t)(wn * 64 + (lane >> 4) * 8 + (lane & 7)) * LDA
                           + (uint32_t)((lane >> 3) & 1) * 16;

    int slot = 0;
    for (int i = 0; i < NSTG64; i++) {
        CP_WAIT(0);
        __syncthreads();
        if (i + 1 < NSTG64) {
            load_stage(sbase + (uint32_t)(slot ^ 1) * STAGE_B, (i + 1) * 64, m0, n0, tid);
            CP_COMMIT();
        }
        const uint32_t st = sbase + (uint32_t)slot * STAGE_B;
#pragma unroll
        for (int kk = 0; kk < 4; kk++) {
            uint32_t aH[2][4], bb[8][2];
#pragma unroll
            for (int mt = 0; mt < 2; mt++)
                ldm_x4(aH[mt][0], aH[mt][1], aH[mt][2], aH[mt][3],
                       st + aRowOfs + (uint32_t)mt * 16 * LDA + kk * 32);
#pragma unroll
            for (int p = 0; p < 4; p++)
                ldm_x4(bb[2 * p][0], bb[2 * p][1], bb[2 * p + 1][0], bb[2 * p + 1][1],
                       st + TILE_B + bRowOfs + (uint32_t)p * 16 * LDA + kk * 32);
#pragma unroll
            for (int mt = 0; mt < 2; mt++)
#pragma unroll
                for (int nt = 0; nt < 8; nt++) mma16816(acc[mt][nt], aH[mt], bb[nt]);
        }
        slot ^= 1;
    }

    // epilogue: per-row sum over n of tanh(S + b1)*W2, reduce, atomicAdd
    const int g = lane >> 2, t4 = lane & 3;
#pragma unroll
    for (int mt = 0; mt < 2; mt++) {
        float sA = 0.f, sB = 0.f;
#pragma unroll
        for (int nt = 0; nt < 8; nt++) {
            int c0 = n0 + wn * 64 + nt * 8 + 2 * t4;
            float b1a = b1[c0], b1b = b1[c0 + 1];
            float w2a = W2[c0], w2b = W2[c0 + 1];
            sA += fast_tanh(acc[mt][nt][0] + b1a) * w2a + fast_tanh(acc[mt][nt][1] + b1b) * w2b;
            sB += fast_tanh(acc[mt][nt][2] + b1a) * w2a + fast_tanh(acc[mt][nt][3] + b1b) * w2b;
        }
        sA += __shfl_xor_sync(0xFFFFFFFF, sA, 1);
        sA += __shfl_xor_sync(0xFFFFFFFF, sA, 2);
        sB += __shfl_xor_sync(0xFFFFFFFF, sB, 1);
        sB += __shfl_xor_sync(0xFFFFFFFF, sB, 2);
        if (t4 == 0) {
            int r = m0 + wm * 32 + mt * 16 + g;
            atomicAdd(&g_a[r], sA);
            atomicAdd(&g_a[r + 8], sB);
        }
    }
}

// ---------------- softmax over W per batch ----------------
__global__ void softmax_kernel() {
    int b = blockIdx.x, t = threadIdx.x;  // 128 threads
    __shared__ float sv[128];
    float v = g_a[b * NW + t];
    sv[t] = v; __syncthreads();
    for (int s = 64; s > 0; s >>= 1) { if (t < s) sv[t] = fmaxf(sv[t], sv[t + s]); __syncthreads(); }
    float m = sv[0]; __syncthreads();
    float e = expf(v - m);
    sv[t] = e; __syncthreads();
    for (int s = 64; s > 0; s >>= 1) { if (t < s) sv[t] += sv[t + s]; __syncthreads(); }
    g_att[b * NW + t] = e / sv[0];
}

// ---------------- attention pool ----------------
__global__ void pool_kernel() {
    int b = blockIdx.y;
    int f = blockIdx.x * 256 + threadIdx.x;
    __shared__ float sat[NW];
    if (threadIdx.x < NW) sat[threadIdx.x] = g_att[b * NW + threadIdx.x];
    __syncthreads();
    if (f >= FEAT) return;
    float acc = 0.f;
    const __half* bh = g_bag + (size_t)b * NW * FEATP + f;
#pragma unroll 4
    for (int w = 0; w < NW; w++)
        acc += sat[w] * __half2float(bh[(size_t)w * FEATP]);
    g_bagz0[b * FEATP + f] = acc;
}

// ---------------- batchnorms ----------------
__global__ void bn_kernel(const float* __restrict__ cc,
                          const float* __restrict__ bn_g, const float* __restrict__ bn_b,
                          const float* __restrict__ bn2_g, const float* __restrict__ bn2_b) {
    int f = blockIdx.x * 256 + threadIdx.x;
    if (f >= FEAT) return;
    float mu = 0.f;
    for (int b = 0; b < NB; b++) mu += g_bagz0[b * FEATP + f];
    mu *= (1.f / NB);
    float var = 0.f;
    for (int b = 0; b < NB; b++) { float d = g_bagz0[b * FEATP + f] - mu; var += d * d; }
    var *= (1.f / NB);
    float inv = rsqrtf(var + 1e-5f);
    float g = bn_g[f], bt = bn_b[f];
    for (int b = 0; b < NB; b++)
        g_bagz[b * FEATP + f] = (g_bagz0[b * FEATP + f] - mu) * inv * g + bt;
    float c0 = cc[f], c1 = cc[FEAT + f];
    float mu2 = 0.5f * (c0 + c1);
    float d0 = c0 - mu2, d1 = c1 - mu2;
    float inv2 = rsqrtf(0.5f * (d0 * d0 + d1 * d1) + 1e-5f);
    float g2 = bn2_g[f], b2v = bn2_b[f];
    g_ccn[f] = d0 * inv2 * g2 + b2v;
    g_ccn[FEATP + f] = d1 * inv2 * g2 + b2v;
}

// ---------------- skinny GEMM: C[M,N] += A[M,K] @ B[K,N], split-K atomics ----
// Unroll-4 B prefetch -> MLP=4 to hide L2 latency.
template <int M>
__global__ __launch_bounds__(256) void skinny_kernel(int selA, int lda,
                                                     const float* __restrict__ B, int ldb,
                                                     int selC, int K, int N) {
    const float* A = (selA == 0) ? g_bagz : (selA == 1) ? g_ccn : g_fcx;
    float* C = (selC == 0) ? g_q : (selC == 1) ? g_k2 : (selC == 2) ? g_v2 : g_t1;
    __shared__ float sA[M][33];
    int tid = threadIdx.x;
    int col = blockIdx.x * 256 + tid;
    int nsplit = gridDim.y;
    int len = (K + nsplit - 1) / nsplit;
    int k0 = blockIdx.y * len;
    int kend = min(K, k0 + len);
    float acc[M];
#pragma unroll
    for (int m = 0; m < M; m++) acc[m] = 0.f;
    for (int kb = k0; kb < kend; kb += 32) {
        int kmax = min(32, kend - kb);
        for (int idx = tid; idx < M * 32; idx += 256) {
            int m = idx >> 5, kk = idx & 31;
            sA[m][kk] = (kk < kmax) ? A[(size_t)m * lda + kb + kk] : 0.f;
        }
        __syncthreads();
        if (col < N) {
            const float* Bp = B + (size_t)kb * ldb + col;
            int kk = 0;
            for (; kk + 4 <= kmax; kk += 4) {
                float bv0 = Bp[0];
                float bv1 = Bp[(size_t)ldb];
                float bv2 = Bp[2 * (size_t)ldb];
                float bv3 = Bp[3 * (size_t)ldb];
                Bp += 4 * (size_t)ldb;
#pragma unroll
                for (int m = 0; m < M; m++) acc[m] += sA[m][kk] * bv0;
#pragma unroll
                for (int m = 0; m < M; m++) acc[m] += sA[m][kk + 1] * bv1;
#pragma unroll
                for (int m = 0; m < M; m++) acc[m] += sA[m][kk + 2] * bv2;
#pragma unroll
                for (int m = 0; m < M; m++) acc[m] += sA[m][kk + 3] * bv3;
            }
            for (; kk < kmax; kk++) {
                float bv = Bp[0]; Bp += (size_t)ldb;
#pragma unroll
                for (int m = 0; m < M; m++) acc[m] += sA[m][kk] * bv;
            }
        }
        __syncthreads();
    }
    if (col < N) {
#pragma unroll
        for (int m = 0; m < M; m++) atomicAdd(&C[(size_t)m * N + col], acc[m]);
    }
}

// ---------------- merged k/v skinny: k2 += ccn@Wk, v2 += ccn@Wq ----------------
__global__ __launch_bounds__(256) void kv_kernel(const float* __restrict__ Wk,
                                                 const float* __restrict__ Wq) {
    __shared__ float sA[2][33];
    int tid = threadIdx.x;
    int col = blockIdx.x * 256 + tid;   // < HH
    int nsplit = gridDim.y;
    int len = (FEAT + nsplit - 1) / nsplit;
    int k0 = blockIdx.y * len;
    int kend = min(FEAT, k0 + len);
    float ak0 = 0.f, ak1 = 0.f, av0 = 0.f, av1 = 0.f;
    for (int kb = k0; kb < kend; kb += 32) {
        int kmax = min(32, kend - kb);
        if (tid < 64) {
            int m = tid >> 5, kk = tid & 31;
            sA[m][kk] = (kk < kmax) ? g_ccn[(size_t)m * FEATP + kb + kk] : 0.f;
        }
        __syncthreads();
        const float* Kp = Wk + (size_t)kb * HH + col;
        const float* Qp = Wq + (size_t)kb * HH + col;
        int kk = 0;
        for (; kk + 2 <= kmax; kk += 2) {
            float k0v = Kp[0], k1v = Kp[HH];
            float q0v = Qp[0], q1v = Qp[HH];
            Kp += 2 * HH; Qp += 2 * HH;
            ak0 += sA[0][kk] * k0v; ak1 += sA[1][kk] * k0v;
            av0 += sA[0][kk] * q0v; av1 += sA[1][kk] * q0v;
            ak0 += sA[0][kk + 1] * k1v; ak1 += sA[1][kk + 1] * k1v;
            av0 += sA[0][kk + 1] * q1v; av1 += sA[1][kk + 1] * q1v;
        }
        for (; kk < kmax; kk++) {
            float kv = Kp[0], qv = Qp[0]; Kp += HH; Qp += HH;
            ak0 += sA[0][kk] * kv; ak1 += sA[1][kk] * kv;
            av0 += sA[0][kk] * qv; av1 += sA[1][kk] * qv;
        }
        __syncthreads();
    }
    atomicAdd(&g_k2[col], ak0);
    atomicAdd(&g_k2[HH + col], ak1);
    atomicAdd(&g_v2[col], av0);
    atomicAdd(&g_v2[HH + col], av1);
}

// ---------------- cross attention ----------------
__global__ void cross_kernel() {
    __shared__ float sQK[64][2];
    __shared__ float sac[64][2];
    int t = threadIdx.x;  // 256
    if (t < 128) {
        int b = t >> 1, r = t & 1;
        const float* qp = g_q + b * HH;
        const float* kp = g_k2 + r * HH;
        float acc = 0.f;
        for (int d = 0; d < HH; d++) acc += qp[d] * kp[d];
        sQK[b][r] = acc * (1.0f / 32.0f);
    }
    __syncthreads();
    if (t < 64) {
        float x0 = sQK[t][0], x1 = sQK[t][1];
        float m = fmaxf(x0, x1);
        float e0 = expf(x0 - m), e1 = expf(x1 - m);
        float inv = 1.f / (e0 + e1);
        sac[t][0] = e0 * inv; sac[t][1] = e1 * inv;
    }
    __syncthreads();
    for (int idx = t; idx < NB * HH; idx += 256) {
        int b = idx >> 10, d = idx & 1023;
        g_fcx[idx] = sac[b][0] * g_v2[d] + sac[b][1] * g_v2[HH + d];
    }
}

// ---------------- classifier head ----------------
__global__ void final_kernel(const float* __restrict__ Wc2, const float* __restrict__ bc2,
                             float* __restrict__ out, int out_size) {
    int b = blockIdx.x, t = threadIdx.x;
    float acc = 0.f;
    for (int d = t; d < DD; d += 256) acc += fmaxf(g_t1[b * DD + d], 0.f) * Wc2[d];
    __shared__ float red[256];
    red[t] = acc; __syncthreads();
    for (int s = 128; s > 0; s >>= 1) { if (t < s) red[t] += red[t + s]; __syncthreads(); }
    if (t == 0) {
        float y = 1.f / (1.f + expf(-(red[0] + bc2[0])));
        out[b] = y;
        if (64 + b < out_size) out[64 + b] = (y >= 0.5f) ? 1.f : 0.f;
    }
}

// ---------------- launch ----------------
extern "C" void kernel_launch(void* const* d_in, const int* in_sizes, int n_in,
                              void* d_out, int out_size) {
    const float* FC    = (const float*)d_in[0];
    const float* cc    = (const float*)d_in[1];
    const float* W1    = (const float*)d_in[2];
    const float* b1    = (const float*)d_in[3];
    const float* W2    = (const float*)d_in[4];
    const float* b2    = (const float*)d_in[5];
    const float* bn_g  = (const float*)d_in[6];
    const float* bn_b  = (const float*)d_in[7];
    const float* bn2_g = (const float*)d_in[8];
    const float* bn2_b = (const float*)d_in[9];
    const float* Wq    = (const float*)d_in[10];
    const float* bq    = (const float*)d_in[11];
    const float* Wk    = (const float*)d_in[12];
    const float* bk    = (const float*)d_in[13];
    const float* Wc1   = (const float*)d_in[14];
    const float* bc1   = (const float*)d_in[15];
    const float* Wc2   = (const float*)d_in[16];
    const float* bc2   = (const float*)d_in[17];
    float* out = (float*)d_out;

    cudaFuncSetAttribute(gemm_mma_kernel, cudaFuncAttributeMaxDynamicSharedMemorySize, GEMM_SMEM);

    init_off_kernel<<<ROI - 1, 128>>>();
    gather_kernel<<<dim3((FEATP + 255) / 256, BW), 256>>>(FC);
    w1t_kernel<<<dim3(FEATP / 32, DD / 32), dim3(32, 8)>>>(W1);
    init_misc_kernel<<<(BW + NB * HH + 4 * HH + NB * DD + 255) / 256, 256>>>(b2, bq, bk, bc1);
    gemm_mma_kernel<<<dim3(8, 64), 256, GEMM_SMEM>>>(b1, W2);
    softmax_kernel<<<NB, 128>>>();
    pool_kernel<<<dim3((FEAT + 255) / 256, NB), 256>>>();
    bn_kernel<<<(FEAT + 255) / 256, 256>>>(cc, bn_g, bn_b, bn2_g, bn2_b);
    skinny_kernel<64><<<dim3(4, 52), 256>>>(0, FEATP, Wq, HH, 0, FEAT, HH);
    kv_kernel<<<dim3(4, 8), 256>>>(Wk, Wq);
    cross_kernel<<<1, 256>>>();
    skinny_kernel<64><<<dim3(4, 8), 256>>>(2, HH, Wc1, DD, 3, HH, DD);
    skinny_kernel<64><<<dim3(4, 52), 256>>>(0, FEATP, Wc1 + (size_t)HH * DD, DD, 3, FEAT, DD);
    final_kernel<<<NB, 256>>>(Wc2, bc2, out, out_size);
}

// round 9
// speedup vs baseline: 1.2657x; 1.0821x over previous
#include <cuda_runtime.h>
#include <cuda_fp16.h>
#include <math.h>
#include <stdint.h>

#define ROI   116
#define FEAT  6670      // ROI*(ROI-1)/2
#define FEATP 6720      // padded to multiple of 64
#define NB    64        // batch
#define NW    128       // bags per batch
#define BW    8192      // NB*NW
#define DD    1024
#define HH    1024
#define NSTG64 (FEATP / 64)  // 105 K-stages of 64

// ---------------- scratch (device globals; no allocation) ----------------
__device__ __align__(16) __half g_bag[(size_t)BW * FEATP];   // 110 MB
__device__ __align__(16) __half g_w1th[(size_t)DD * FEATP];  // 13.8 MB  [N][K]
__device__ int   g_off[FEAT];
__device__ float g_a[BW];
__device__ float g_att[BW];
__device__ float g_bagz0[NB * FEATP];
__device__ float g_bagz[NB * FEATP];
__device__ float g_ccn[2 * FEATP];
__device__ float g_q[NB * HH];
__device__ float g_k2[2 * HH];
__device__ float g_v2[2 * HH];
__device__ float g_fcx[NB * HH];
__device__ float g_t1[NB * DD];

// ---------------- PTX helpers (generic, sm_80-level) ----------------
__device__ __forceinline__ uint32_t smem_u32(const void* p) {
    uint32_t a;
    asm("{ .reg .u64 t; cvta.to.shared.u64 t, %1; cvt.u32.u64 %0, t; }" : "=r"(a) : "l"(p));
    return a;
}
#define CP_ASYNC16(dst, src) \
    asm volatile("cp.async.cg.shared.global [%0], [%1], 16;" \
                 :: "r"(dst), "l"(src) : "memory")
#define CP_COMMIT() asm volatile("cp.async.commit_group;" ::: "memory")
#define CP_WAIT(n)  asm volatile("cp.async.wait_group %0;" :: "n"(n) : "memory")

__device__ __forceinline__ void ldm_x4(uint32_t& r0, uint32_t& r1, uint32_t& r2, uint32_t& r3,
                                       uint32_t addr) {
    asm volatile("ldmatrix.sync.aligned.m8n8.x4.shared.b16 {%0,%1,%2,%3}, [%4];"
                 : "=r"(r0), "=r"(r1), "=r"(r2), "=r"(r3) : "r"(addr));
}
__device__ __forceinline__ void mma16816(float* c, const uint32_t* a, const uint32_t* b) {
    asm volatile(
        "mma.sync.aligned.m16n8k16.row.col.f32.f16.f16.f32 "
        "{%0,%1,%2,%3}, {%4,%5,%6,%7}, {%8,%9}, {%0,%1,%2,%3};"
        : "+f"(c[0]), "+f"(c[1]), "+f"(c[2]), "+f"(c[3])
        : "r"(a[0]), "r"(a[1]), "r"(a[2]), "r"(a[3]), "r"(b[0]), "r"(b[1]));
}
__device__ __forceinline__ float fast_tanh(float x) {
    float e = __expf(2.0f * x);
    return 1.0f - 2.0f / (e + 1.0f);
}

// ---------------- triu index table ----------------
__global__ void init_off_kernel() {
    int i = blockIdx.x;
    int base = i * (ROI - 1) - i * (i - 1) / 2;
    int cnt = ROI - 1 - i;
    for (int jj = threadIdx.x; jj < cnt; jj += blockDim.x)
        g_off[base + jj] = i * ROI + (i + 1 + jj);
}

// ---------------- gather -> fp16 ----------------
__global__ void gather_kernel(const float* __restrict__ FC) {
    int bw = blockIdx.y;
    int f = blockIdx.x * 256 + threadIdx.x;
    if (f < FEATP) {
        float v = 0.f;
        if (f < FEAT) v = FC[(size_t)bw * (ROI * ROI) + g_off[f]];
        g_bag[(size_t)bw * FEATP + f] = __float2half_rn(v);
    }
}

// ---------------- W1 -> W1T fp16 ([N][K], padded); also inits g_a = b2 ----
__global__ void w1t_kernel(const float* __restrict__ W1, const float* __restrict__ b2) {
    __shared__ float t[32][33];
    int kb = blockIdx.x * 32, nb = blockIdx.y * 32;
    int tx = threadIdx.x, ty = threadIdx.y;
    if (blockIdx.x == 0 && blockIdx.y == 0) {
        int tid = ty * 32 + tx;
        float v = b2[0];
        for (int i = tid; i < BW; i += 256) g_a[i] = v;
    }
#pragma unroll
    for (int i = 0; i < 32; i += 8) {
        int k = kb + ty + i;
        t[ty + i][tx] = (k < FEAT) ? W1[(size_t)k * DD + nb + tx] : 0.f;
    }
    __syncthreads();
#pragma unroll
    for (int i = 0; i < 32; i += 8) {
        float v = t[tx][ty + i];
        g_w1th[(size_t)(nb + ty + i) * FEATP + kb + tx] = __float2half_rn(v);
    }
}

// ---------------- init biases into accumulator buffers (post-GEMM ones) ----
__global__ void init_misc_kernel(const float* __restrict__ bq,
                                 const float* __restrict__ bk,
                                 const float* __restrict__ bc1) {
    int idx = blockIdx.x * 256 + threadIdx.x;
    if (idx < NB * HH) { g_q[idx] = bq[idx & (HH - 1)]; return; }
    idx -= NB * HH;
    if (idx < 2 * HH) { g_k2[idx] = bk[idx & (HH - 1)]; return; }
    idx -= 2 * HH;
    if (idx < 2 * HH) { g_v2[idx] = bq[idx & (HH - 1)]; return; }
    idx -= 2 * HH;
    if (idx < NB * DD) { g_t1[idx] = bc1[idx & (DD - 1)]; return; }
}

// ---------------- HMMA GEMM: S = bag @ W1T^T (fp16), fused tanh/W2 epi ----
// CTA 128x128, 8 warps (4Mx2N), warp tile 32x64. K-stage 64, 3-stage
// pipeline (CP_WAIT(1)), one __syncthreads per stage. rows 144B.
#define LDA       144
#define TILE_B    18432               // 128 rows x 144B
#define STAGE_B   (2 * TILE_B)        // A + B = 36864
#define GEMM_SMEM (3 * STAGE_B)       // 110592

__device__ __forceinline__ void load_stage(uint32_t sdst, int k0, int m0, int n0, int tid) {
    int row = tid >> 1;
    int cb = (tid & 1) * 64;          // byte offset within 128B row half
    uint32_t so = sdst + row * LDA + cb;
    size_t ga = ((size_t)(m0 + row) * FEATP + k0) * 2 + cb;
    size_t gb = ((size_t)(n0 + row) * FEATP + k0) * 2 + cb;
    unsigned long long pa = __cvta_generic_to_global((const char*)g_bag + ga);
    unsigned long long pb = __cvta_generic_to_global((const char*)g_w1th + gb);
    CP_ASYNC16(so,      pa);      CP_ASYNC16(so + 16, pa + 16);
    CP_ASYNC16(so + 32, pa + 32); CP_ASYNC16(so + 48, pa + 48);
    so += TILE_B;
    CP_ASYNC16(so,      pb);      CP_ASYNC16(so + 16, pb + 16);
    CP_ASYNC16(so + 32, pb + 32); CP_ASYNC16(so + 48, pb + 48);
}

__global__ __launch_bounds__(256, 2) void gemm_mma_kernel(const float* __restrict__ b1,
                                                          const float* __restrict__ W2) {
    extern __shared__ char sm[];
    const uint32_t sbase = smem_u32(sm);
    const int tid = threadIdx.x, lane = tid & 31, wid = tid >> 5;
    const int wm = wid & 3, wn = wid >> 2;        // 4 M-warps x 2 N-warps
    const int n0 = blockIdx.x * 128, m0 = blockIdx.y * 128;

    float acc[2][8][4];
#pragma unroll
    for (int mt = 0; mt < 2; mt++)
#pragma unroll
        for (int nt = 0; nt < 8; nt++)
#pragma unroll
            for (int c = 0; c < 4; c++) acc[mt][nt][c] = 0.f;

    load_stage(sbase, 0, m0, n0, tid);             CP_COMMIT();
    load_stage(sbase + STAGE_B, 64, m0, n0, tid);  CP_COMMIT();

    const uint32_t aRowOfs = (uint32_t)(wm * 32 + ((lane >> 3) & 1) * 8 + (lane & 7)) * LDA
                           + (uint32_t)(lane >> 4) * 16;
    const uint32_t bRowOfs = (uint32_t)(wn * 64 + (lane >> 4) * 8 + (lane & 7)) * LDA
                           + (uint32_t)((lane >> 3) & 1) * 16;

    int slot = 0;
    for (int i = 0; i < NSTG64; i++) {
        if (i + 1 < NSTG64) { CP_WAIT(1); } else { CP_WAIT(0); }
        __syncthreads();
        if (i + 2 < NSTG64) {
            int ns = slot + 2; if (ns >= 3) ns -= 3;
            load_stage(sbase + (uint32_t)ns * STAGE_B, (i + 2) * 64, m0, n0, tid);
            CP_COMMIT();
        }
        const uint32_t st = sbase + (uint32_t)slot * STAGE_B;
#pragma unroll
        for (int kk = 0; kk < 4; kk++) {
            uint32_t aH[2][4], bb[8][2];
#pragma unroll
            for (int mt = 0; mt < 2; mt++)
                ldm_x4(aH[mt][0], aH[mt][1], aH[mt][2], aH[mt][3],
                       st + aRowOfs + (uint32_t)mt * 16 * LDA + kk * 32);
#pragma unroll
            for (int p = 0; p < 4; p++)
                ldm_x4(bb[2 * p][0], bb[2 * p][1], bb[2 * p + 1][0], bb[2 * p + 1][1],
                       st + TILE_B + bRowOfs + (uint32_t)p * 16 * LDA + kk * 32);
#pragma unroll
            for (int mt = 0; mt < 2; mt++)
#pragma unroll
                for (int nt = 0; nt < 8; nt++) mma16816(acc[mt][nt], aH[mt], bb[nt]);
        }
        if (++slot == 3) slot = 0;
    }

    // epilogue: per-row sum over n of tanh(S + b1)*W2, reduce, atomicAdd
    const int g = lane >> 2, t4 = lane & 3;
#pragma unroll
    for (int mt = 0; mt < 2; mt++) {
        float sA = 0.f, sB = 0.f;
#pragma unroll
        for (int nt = 0; nt < 8; nt++) {
            int c0 = n0 + wn * 64 + nt * 8 + 2 * t4;
            float b1a = b1[c0], b1b = b1[c0 + 1];
            float w2a = W2[c0], w2b = W2[c0 + 1];
            sA += fast_tanh(acc[mt][nt][0] + b1a) * w2a + fast_tanh(acc[mt][nt][1] + b1b) * w2b;
            sB += fast_tanh(acc[mt][nt][2] + b1a) * w2a + fast_tanh(acc[mt][nt][3] + b1b) * w2b;
        }
        sA += __shfl_xor_sync(0xFFFFFFFF, sA, 1);
        sA += __shfl_xor_sync(0xFFFFFFFF, sA, 2);
        sB += __shfl_xor_sync(0xFFFFFFFF, sB, 1);
        sB += __shfl_xor_sync(0xFFFFFFFF, sB, 2);
        if (t4 == 0) {
            int r = m0 + wm * 32 + mt * 16 + g;
            atomicAdd(&g_a[r], sA);
            atomicAdd(&g_a[r + 8], sB);
        }
    }
}

// ---------------- softmax over W per batch ----------------
__global__ void softmax_kernel() {
    int b = blockIdx.x, t = threadIdx.x;  // 128 threads
    __shared__ float sv[128];
    float v = g_a[b * NW + t];
    sv[t] = v; __syncthreads();
    for (int s = 64; s > 0; s >>= 1) { if (t < s) sv[t] = fmaxf(sv[t], sv[t + s]); __syncthreads(); }
    float m = sv[0]; __syncthreads();
    float e = expf(v - m);
    sv[t] = e; __syncthreads();
    for (int s = 64; s > 0; s >>= 1) { if (t < s) sv[t] += sv[t + s]; __syncthreads(); }
    g_att[b * NW + t] = e / sv[0];
}

// ---------------- attention pool ----------------
__global__ void pool_kernel() {
    int b = blockIdx.y;
    int f = blockIdx.x * 256 + threadIdx.x;
    __shared__ float sat[NW];
    if (threadIdx.x < NW) sat[threadIdx.x] = g_att[b * NW + threadIdx.x];
    __syncthreads();
    if (f >= FEAT) return;
    float acc = 0.f;
    const __half* bh = g_bag + (size_t)b * NW * FEATP + f;
#pragma unroll 4
    for (int w = 0; w < NW; w++)
        acc += sat[w] * __half2float(bh[(size_t)w * FEATP]);
    g_bagz0[b * FEATP + f] = acc;
}

// ---------------- batchnorms ----------------
__global__ void bn_kernel(const float* __restrict__ cc,
                          const float* __restrict__ bn_g, const float* __restrict__ bn_b,
                          const float* __restrict__ bn2_g, const float* __restrict__ bn2_b) {
    int f = blockIdx.x * 256 + threadIdx.x;
    if (f >= FEAT) return;
    float mu = 0.f;
    for (int b = 0; b < NB; b++) mu += g_bagz0[b * FEATP + f];
    mu *= (1.f / NB);
    float var = 0.f;
    for (int b = 0; b < NB; b++) { float d = g_bagz0[b * FEATP + f] - mu; var += d * d; }
    var *= (1.f / NB);
    float inv = rsqrtf(var + 1e-5f);
    float g = bn_g[f], bt = bn_b[f];
    for (int b = 0; b < NB; b++)
        g_bagz[b * FEATP + f] = (g_bagz0[b * FEATP + f] - mu) * inv * g + bt;
    float c0 = cc[f], c1 = cc[FEAT + f];
    float mu2 = 0.5f * (c0 + c1);
    float d0 = c0 - mu2, d1 = c1 - mu2;
    float inv2 = rsqrtf(0.5f * (d0 * d0 + d1 * d1) + 1e-5f);
    float g2 = bn2_g[f], b2v = bn2_b[f];
    g_ccn[f] = d0 * inv2 * g2 + b2v;
    g_ccn[FEATP + f] = d1 * inv2 * g2 + b2v;
}

// ---------------- skinny GEMM: C[M,N] += A[M,K] @ B[K,N], split-K atomics ----
template <int M>
__global__ __launch_bounds__(256) void skinny_kernel(int selA, int lda,
                                                     const float* __restrict__ B, int ldb,
                                                     int selC, int K, int N) {
    const float* A = (selA == 0) ? g_bagz : (selA == 1) ? g_ccn : g_fcx;
    float* C = (selC == 0) ? g_q : (selC == 1) ? g_k2 : (selC == 2) ? g_v2 : g_t1;
    __shared__ float sA[M][33];
    int tid = threadIdx.x;
    int col = blockIdx.x * 256 + tid;
    int nsplit = gridDim.y;
    int len = (K + nsplit - 1) / nsplit;
    int k0 = blockIdx.y * len;
    int kend = min(K, k0 + len);
    float acc[M];
#pragma unroll
    for (int m = 0; m < M; m++) acc[m] = 0.f;
    for (int kb = k0; kb < kend; kb += 32) {
        int kmax = min(32, kend - kb);
        for (int idx = tid; idx < M * 32; idx += 256) {
            int m = idx >> 5, kk = idx & 31;
            sA[m][kk] = (kk < kmax) ? A[(size_t)m * lda + kb + kk] : 0.f;
        }
        __syncthreads();
        if (col < N) {
            const float* Bp = B + (size_t)kb * ldb + col;
            int kk = 0;
            for (; kk + 4 <= kmax; kk += 4) {
                float bv0 = Bp[0];
                float bv1 = Bp[(size_t)ldb];
                float bv2 = Bp[2 * (size_t)ldb];
                float bv3 = Bp[3 * (size_t)ldb];
                Bp += 4 * (size_t)ldb;
#pragma unroll
                for (int m = 0; m < M; m++) acc[m] += sA[m][kk] * bv0;
#pragma unroll
                for (int m = 0; m < M; m++) acc[m] += sA[m][kk + 1] * bv1;
#pragma unroll
                for (int m = 0; m < M; m++) acc[m] += sA[m][kk + 2] * bv2;
#pragma unroll
                for (int m = 0; m < M; m++) acc[m] += sA[m][kk + 3] * bv3;
            }
            for (; kk < kmax; kk++) {
                float bv = Bp[0]; Bp += (size_t)ldb;
#pragma unroll
                for (int m = 0; m < M; m++) acc[m] += sA[m][kk] * bv;
            }
        }
        __syncthreads();
    }
    if (col < N) {
#pragma unroll
        for (int m = 0; m < M; m++) atomicAdd(&C[(size_t)m * N + col], acc[m]);
    }
}

// ---------------- merged k/v skinny: k2 += ccn@Wk, v2 += ccn@Wq ----------------
__global__ __launch_bounds__(256) void kv_kernel(const float* __restrict__ Wk,
                                                 const float* __restrict__ Wq) {
    __shared__ float sA[2][33];
    int tid = threadIdx.x;
    int col = blockIdx.x * 256 + tid;   // < HH
    int nsplit = gridDim.y;
    int len = (FEAT + nsplit - 1) / nsplit;
    int k0 = blockIdx.y * len;
    int kend = min(FEAT, k0 + len);
    float ak0 = 0.f, ak1 = 0.f, av0 = 0.f, av1 = 0.f;
    for (int kb = k0; kb < kend; kb += 32) {
        int kmax = min(32, kend - kb);
        if (tid < 64) {
            int m = tid >> 5, kk = tid & 31;
            sA[m][kk] = (kk < kmax) ? g_ccn[(size_t)m * FEATP + kb + kk] : 0.f;
        }
        __syncthreads();
        const float* Kp = Wk + (size_t)kb * HH + col;
        const float* Qp = Wq + (size_t)kb * HH + col;
        int kk = 0;
        for (; kk + 2 <= kmax; kk += 2) {
            float k0v = Kp[0], k1v = Kp[HH];
            float q0v = Qp[0], q1v = Qp[HH];
            Kp += 2 * HH; Qp += 2 * HH;
            ak0 += sA[0][kk] * k0v; ak1 += sA[1][kk] * k0v;
            av0 += sA[0][kk] * q0v; av1 += sA[1][kk] * q0v;
            ak0 += sA[0][kk + 1] * k1v; ak1 += sA[1][kk + 1] * k1v;
            av0 += sA[0][kk + 1] * q1v; av1 += sA[1][kk + 1] * q1v;
        }
        for (; kk < kmax; kk++) {
            float kv = Kp[0], qv = Qp[0]; Kp += HH; Qp += HH;
            ak0 += sA[0][kk] * kv; ak1 += sA[1][kk] * kv;
            av0 += sA[0][kk] * qv; av1 += sA[1][kk] * qv;
        }
        __syncthreads();
    }
    atomicAdd(&g_k2[col], ak0);
    atomicAdd(&g_k2[HH + col], ak1);
    atomicAdd(&g_v2[col], av0);
    atomicAdd(&g_v2[HH + col], av1);
}

// ---------------- cross attention ----------------
__global__ void cross_kernel() {
    __shared__ float sQK[64][2];
    __shared__ float sac[64][2];
    int t = threadIdx.x;  // 256
    if (t < 128) {
        int b = t >> 1, r = t & 1;
        const float* qp = g_q + b * HH;
        const float* kp = g_k2 + r * HH;
        float acc = 0.f;
        for (int d = 0; d < HH; d++) acc += qp[d] * kp[d];
        sQK[b][r] = acc * (1.0f / 32.0f);
    }
    __syncthreads();
    if (t < 64) {
        float x0 = sQK[t][0], x1 = sQK[t][1];
        float m = fmaxf(x0, x1);
        float e0 = expf(x0 - m), e1 = expf(x1 - m);
        float inv = 1.f / (e0 + e1);
        sac[t][0] = e0 * inv; sac[t][1] = e1 * inv;
    }
    __syncthreads();
    for (int idx = t; idx < NB * HH; idx += 256) {
        int b = idx >> 10, d = idx & 1023;
        g_fcx[idx] = sac[b][0] * g_v2[d] + sac[b][1] * g_v2[HH + d];
    }
}

// ---------------- classifier head ----------------
__global__ void final_kernel(const float* __restrict__ Wc2, const float* __restrict__ bc2,
                             float* __restrict__ out, int out_size) {
    int b = blockIdx.x, t = threadIdx.x;
    float acc = 0.f;
    for (int d = t; d < DD; d += 256) acc += fmaxf(g_t1[b * DD + d], 0.f) * Wc2[d];
    __shared__ float red[256];
    red[t] = acc; __syncthreads();
    for (int s = 128; s > 0; s >>= 1) { if (t < s) red[t] += red[t + s]; __syncthreads(); }
    if (t == 0) {
        float y = 1.f / (1.f + expf(-(red[0] + bc2[0])));
        out[b] = y;
        if (64 + b < out_size) out[64 + b] = (y >= 0.5f) ? 1.f : 0.f;
    }
}

// ---------------- launch ----------------
extern "C" void kernel_launch(void* const* d_in, const int* in_sizes, int n_in,
                              void* d_out, int out_size) {
    const float* FC    = (const float*)d_in[0];
    const float* cc    = (const float*)d_in[1];
    const float* W1    = (const float*)d_in[2];
    const float* b1    = (const float*)d_in[3];
    const float* W2    = (const float*)d_in[4];
    const float* b2    = (const float*)d_in[5];
    const float* bn_g  = (const float*)d_in[6];
    const float* bn_b  = (const float*)d_in[7];
    const float* bn2_g = (const float*)d_in[8];
    const float* bn2_b = (const float*)d_in[9];
    const float* Wq    = (const float*)d_in[10];
    const float* bq    = (const float*)d_in[11];
    const float* Wk    = (const float*)d_in[12];
    const float* bk    = (const float*)d_in[13];
    const float* Wc1   = (const float*)d_in[14];
    const float* bc1   = (const float*)d_in[15];
    const float* Wc2   = (const float*)d_in[16];
    const float* bc2   = (const float*)d_in[17];
    float* out = (float*)d_out;

    cudaFuncSetAttribute(gemm_mma_kernel, cudaFuncAttributeMaxDynamicSharedMemorySize, GEMM_SMEM);

    init_off_kernel<<<ROI - 1, 128>>>();                                   // 1
    gather_kernel<<<dim3((FEATP + 255) / 256, BW), 256>>>(FC);             // 2
    w1t_kernel<<<dim3(FEATP / 32, DD / 32), dim3(32, 8)>>>(W1, b2);        // 3
    gemm_mma_kernel<<<dim3(8, 64), 256, GEMM_SMEM>>>(b1, W2);              // 4 (ncu slot)
    init_misc_kernel<<<(NB * HH + 4 * HH + NB * DD + 255) / 256, 256>>>(bq, bk, bc1);
    softmax_kernel<<<NB, 128>>>();
    pool_kernel<<<dim3((FEAT + 255) / 256, NB), 256>>>();
    bn_kernel<<<(FEAT + 255) / 256, 256>>>(cc, bn_g, bn_b, bn2_g, bn2_b);
    skinny_kernel<64><<<dim3(4, 104), 256>>>(0, FEATP, Wq, HH, 0, FEAT, HH);
    kv_kernel<<<dim3(4, 16), 256>>>(Wk, Wq);
    cross_kernel<<<1, 256>>>();
    skinny_kernel<64><<<dim3(4, 16), 256>>>(2, HH, Wc1, DD, 3, HH, DD);
    skinny_kernel<64><<<dim3(4, 104), 256>>>(0, FEATP, Wc1 + (size_t)HH * DD, DD, 3, FEAT, DD);
    final_kernel<<<NB, 256>>>(Wc2, bc2, out, out_size);
}